// round 4
// baseline (speedup 1.0000x reference)
#include <cuda_runtime.h>
#include <cstdint>

#define Bb 64
#define Hh 1024
#define Ss 512

// Scratch: transposed seq_states [B][S][H] and per-(b,s) sum of squares.
__device__ float g_trans[(size_t)Bb * Ss * Hh];   // 128 MB
__device__ float g_ss[Bb * Ss];

// ---------------------------------------------------------------------------
// Kernel 0: zero the norm accumulators (graph replays re-run this each launch)
// ---------------------------------------------------------------------------
__global__ void zero_ss_kernel() {
    int i = blockIdx.x * blockDim.x + threadIdx.x;
    if (i < Bb * Ss) g_ss[i] = 0.0f;
}

// ---------------------------------------------------------------------------
// Kernel 1: transpose (B,H,S) -> (B,S,H) + fused sum-of-squares per (b,s).
// Block (32,8), each block handles a 32x32 (s,h) tile. Coalesced both sides.
// ---------------------------------------------------------------------------
__global__ void transpose_kernel(const float* __restrict__ seq) {
    __shared__ float tile[32][33];
    const int tx = threadIdx.x, ty = threadIdx.y;
    const int b  = blockIdx.z;
    const int s0 = blockIdx.x * 32, h0 = blockIdx.y * 32;

    const float* src = seq + (size_t)b * Hh * Ss;
#pragma unroll
    for (int j = 0; j < 4; j++) {
        int h = h0 + ty + j * 8;
        tile[ty + j * 8][tx] = src[(size_t)h * Ss + (s0 + tx)];   // coalesced in s
    }
    __syncthreads();

    float* dst = g_trans + (size_t)b * Ss * Hh;
#pragma unroll
    for (int j = 0; j < 4; j++) {
        int sl = ty + j * 8;
        float v = tile[tx][sl];                                   // conflict-free (pad 33)
        dst[(size_t)(s0 + sl) * Hh + (h0 + tx)] = v;              // coalesced in h
        // warp lanes (tx) all share this s -> full 32-h partial in one butterfly
        float p = v * v;
#pragma unroll
        for (int o = 16; o; o >>= 1) p += __shfl_xor_sync(0xffffffffu, p, o);
        if (tx == 0) atomicAdd(&g_ss[b * Ss + s0 + sl], p);
    }
}

// ---------------------------------------------------------------------------
// Kernel 2: the sequential scan. One CTA per batch, 128 threads, 8 h-elems
// per thread in registers. s-tiles (T=4 steps = 16KB) double-buffered via
// cp.async from the transposed (contiguous) layout.
// ---------------------------------------------------------------------------
#define T_TILE 4
#define NTILES (Ss / T_TILE)     // 128
#define THREADS 128
#define SB_FLOATS (2 * T_TILE * Hh)              // 8192 floats (32 KB)
#define SMEM_FLOATS (SB_FLOATS + Ss + Ss + 16)   // + snorm + mask + part

__device__ __forceinline__ void cpa16(uint32_t dst, const float* src) {
    asm volatile("cp.async.cg.shared.global [%0], [%1], 16;\n"
                 :: "r"(dst), "l"(src));
}

__global__ __launch_bounds__(THREADS, 1)
void scan_kernel(const float* __restrict__ tree,
                 const float* __restrict__ mask_in,
                 float* __restrict__ out) {
    __shared__ float sm[SMEM_FLOATS];
    float* sbuf  = sm;                    // [2][T_TILE*Hh]
    float* snorm = sm + SB_FLOATS;        // [512]
    float* smask = snorm + Ss;            // [512]
    float* part  = smask + Ss;            // [2][8] : (dot,hh) per warp, double-buffered

    const int tid  = threadIdx.x;
    const int b    = blockIdx.x;
    const int lane = tid & 31;
    const int warp = tid >> 5;
    const uint32_t sb_u32 = (uint32_t)__cvta_generic_to_shared(sbuf);

    // Preload per-step norms (sqrt once) and mask into smem.
    for (int i = tid; i < Ss; i += THREADS) {
        snorm[i] = sqrtf(g_ss[b * Ss + i]);
        smask[i] = mask_in[b * Ss + i];
    }

    // h state in registers: thread owns h = {tid*4+k, 512+tid*4+k}, k=0..3
    float h[8];
    {
        float4 a = *(const float4*)(tree + b * Hh + tid * 4);
        float4 c = *(const float4*)(tree + b * Hh + 512 + tid * 4);
        h[0]=a.x; h[1]=a.y; h[2]=a.z; h[3]=a.w;
        h[4]=c.x; h[5]=c.y; h[6]=c.z; h[7]=c.w;
    }

    const float* gsrc = g_trans + (size_t)b * Ss * Hh;

    // Prefetch tile 0 into buffer 0.
    {
#pragma unroll
        for (int i = 0; i < 8; i++) {
            int c = tid + i * THREADS;                 // 1024 x 16B chunks
            cpa16(sb_u32 + c * 16, gsrc + c * 4);
        }
        asm volatile("cp.async.commit_group;\n");
    }

    int pp = 0;  // active-step parity for the cross-warp partial buffer
    for (int t = 0; t < Ss; t++) {
        const int sl = t & (T_TILE - 1);
        const int k  = t >> 2;
        if (sl == 0) {
            asm volatile("cp.async.wait_group 0;\n" ::: "memory");
            __syncthreads();                           // tile k visible; tile k-1 free
            const int nk = k + 1;
            if (nk < NTILES) {
                const float*   srcp = gsrc + (size_t)nk * T_TILE * Hh;
                const uint32_t d = sb_u32 + (uint32_t)((nk & 1) * T_TILE * Hh * 4);
#pragma unroll
                for (int i = 0; i < 8; i++) {
                    int c = tid + i * THREADS;
                    cpa16(d + c * 16, srcp + c * 4);
                }
                asm volatile("cp.async.commit_group;\n");
            }
        }

        const float m = smask[t];          // uniform across the block
        if (m != 0.0f) {
            const float* sp = sbuf + (k & 1) * (T_TILE * Hh) + sl * Hh;
            float4 s0 = *(const float4*)(sp + tid * 4);
            float4 s1 = *(const float4*)(sp + 512 + tid * 4);
            float sv[8] = {s0.x, s0.y, s0.z, s0.w, s1.x, s1.y, s1.z, s1.w};

            float dot = 0.0f, hh = 0.0f;
#pragma unroll
            for (int i = 0; i < 8; i++) {
                dot = fmaf(h[i], sv[i], dot);
                hh  = fmaf(h[i], h[i], hh);
            }
#pragma unroll
            for (int o = 16; o; o >>= 1) {
                dot += __shfl_xor_sync(0xffffffffu, dot, o);
                hh  += __shfl_xor_sync(0xffffffffu, hh,  o);
            }
            if (lane == 0) {
                part[pp * 8 + warp * 2]     = dot;
                part[pp * 8 + warp * 2 + 1] = hh;
            }
            __syncthreads();
            float4 p0 = *(const float4*)(part + pp * 8);
            float4 p1 = *(const float4*)(part + pp * 8 + 4);
            float D  = (p0.x + p0.z) + (p1.x + p1.z);
            float HH = (p0.y + p0.w) + (p1.y + p1.w);

            float cosv = D / fmaxf(sqrtf(HH) * snorm[t], 1e-8f);
            float a = 1.0f - cosv;         // h + (s - h*cos) = h*(1-cos) + s
#pragma unroll
            for (int i = 0; i < 8; i++)
                h[i] = fminf(fmaxf(fmaf(h[i], a, sv[i]), -1.0f), 1.0f);
            pp ^= 1;
        } else {
            // reference clips even when mask == 0
#pragma unroll
            for (int i = 0; i < 8; i++)
                h[i] = fminf(fmaxf(h[i], -1.0f), 1.0f);
        }
    }

    float* o = out + b * Hh;
    *(float4*)(o + tid * 4)       = make_float4(h[0], h[1], h[2], h[3]);
    *(float4*)(o + 512 + tid * 4) = make_float4(h[4], h[5], h[6], h[7]);
}

// ---------------------------------------------------------------------------
extern "C" void kernel_launch(void* const* d_in, const int* in_sizes, int n_in,
                              void* d_out, int out_size) {
    const float* tree = (const float*)d_in[0];   // (B,H)
    const float* seq  = (const float*)d_in[1];   // (B,H,S)
    const float* mask = (const float*)d_in[2];   // (B,S)
    float* out = (float*)d_out;                  // (B,H)

    zero_ss_kernel<<<(Bb * Ss + 255) / 256, 256>>>();
    transpose_kernel<<<dim3(Ss / 32, Hh / 32, Bb), dim3(32, 8)>>>(seq);
    scan_kernel<<<Bb, THREADS>>>(tree, mask, out);
}

// round 6
// speedup vs baseline: 1.2409x; 1.2409x over previous
#include <cuda_runtime.h>
#include <cstdint>

#define Bb 64
#define Hh 1024
#define Ss 512

// Scratch: transposed seq_states [B][S][H] and per-(b,s,hblk) partial sums of squares.
__device__ float g_trans[(size_t)Bb * Ss * Hh];   // 128 MB
__device__ float g_ssp[Bb * Ss * 32];             // 4 MB, no zeroing needed

// ---------------------------------------------------------------------------
// Kernel 1: transpose (B,H,S) -> (B,S,H) + per-block 32-h partial sum of
// squares written to a private slot (no atomics, no zero pass).
// Block (32,8): one 32x32 (s,h) tile. Coalesced on both sides.
// ---------------------------------------------------------------------------
__global__ void transpose_kernel(const float* __restrict__ seq) {
    __shared__ float tile[32][33];
    const int tx = threadIdx.x, ty = threadIdx.y;
    const int b  = blockIdx.z;
    const int s0 = blockIdx.x * 32, h0 = blockIdx.y * 32;

    const float* src = seq + (size_t)b * Hh * Ss;
#pragma unroll
    for (int j = 0; j < 4; j++) {
        int h = h0 + ty + j * 8;
        tile[ty + j * 8][tx] = src[(size_t)h * Ss + (s0 + tx)];   // coalesced in s
    }
    __syncthreads();

    float* dst = g_trans + (size_t)b * Ss * Hh;
#pragma unroll
    for (int j = 0; j < 4; j++) {
        int sl = ty + j * 8;
        float v = tile[tx][sl];                                   // conflict-free (pad 33)
        dst[(size_t)(s0 + sl) * Hh + (h0 + tx)] = v;              // coalesced in h
        // warp lanes (tx) all share this s -> 32-h partial in one butterfly
        float p = v * v;
#pragma unroll
        for (int o = 16; o; o >>= 1) p += __shfl_xor_sync(0xffffffffu, p, o);
        if (tx == 0)
            g_ssp[(size_t)(b * Ss + s0 + sl) * 32 + blockIdx.y] = p;
    }
}

// ---------------------------------------------------------------------------
// Kernel 2: the sequential scan. One CTA per batch, 128 threads, 8 h-elems
// per thread in registers. s-tiles (T=4 steps = 16KB) double-buffered via
// cp.async from the transposed (contiguous) layout.
// ---------------------------------------------------------------------------
#define T_TILE 4
#define NTILES (Ss / T_TILE)     // 128
#define THREADS 128
#define SB_FLOATS (2 * T_TILE * Hh)                           // 8192 floats (32 KB)
#define SMEM_FLOATS (SB_FLOATS + (Ss + 8) + (Ss + 8) + 16)

__device__ __forceinline__ void cpa16(uint32_t dst, const float* src) {
    asm volatile("cp.async.cg.shared.global [%0], [%1], 16;\n"
                 :: "r"(dst), "l"(src));
}

__global__ __launch_bounds__(THREADS, 1)
void scan_kernel(const float* __restrict__ tree,
                 const float* __restrict__ mask_in,
                 float* __restrict__ out) {
    __shared__ float sm[SMEM_FLOATS];
    float* sbuf  = sm;                    // [2][T_TILE*Hh]
    float* ssinv = sm + SB_FLOATS;        // [Ss+8] : 1/||s_t|| (rsqrt of sum sq)
    float* smask = ssinv + (Ss + 8);      // [Ss+8]
    float* part  = smask + (Ss + 8);      // [2][8] : (dot,hh) per warp, double-buffered

    const int tid  = threadIdx.x;
    const int b    = blockIdx.x;
    const int lane = tid & 31;
    const int warp = tid >> 5;
    const uint32_t sb_u32 = (uint32_t)__cvta_generic_to_shared(sbuf);

    const float* gsrc = g_trans + (size_t)b * Ss * Hh;

    // Prefetch tile 0 into buffer 0 first (gets the LSU going early).
    {
#pragma unroll
        for (int i = 0; i < 8; i++) {
            int c = tid + i * THREADS;                 // 1024 x 16B chunks
            cpa16(sb_u32 + c * 16, gsrc + c * 4);
        }
        asm volatile("cp.async.commit_group;\n");
    }

    // Preload per-step inverse norms (sum 32 partials, one rsqrt) and mask.
    for (int i = tid; i < Ss; i += THREADS) {
        const float4* p = (const float4*)(g_ssp + ((size_t)(b * Ss + i) << 5));
        float acc = 0.0f;
#pragma unroll
        for (int j = 0; j < 8; j++) {
            float4 v = p[j];
            acc += (v.x + v.y) + (v.z + v.w);
        }
        ssinv[i] = rsqrtf(fmaxf(acc, 1e-30f));
        smask[i] = mask_in[b * Ss + i];
    }
    if (tid < 8) { ssinv[Ss + tid] = 1.0f; smask[Ss + tid] = 0.0f; }  // pad for lookahead

    // h state in registers: thread owns h = {tid*4+k, 512+tid*4+k}, k=0..3
    float h[8];
    {
        float4 a = *(const float4*)(tree + b * Hh + tid * 4);
        float4 c = *(const float4*)(tree + b * Hh + 512 + tid * 4);
        h[0]=a.x; h[1]=a.y; h[2]=a.z; h[3]=a.w;
        h[4]=c.x; h[5]=c.y; h[6]=c.z; h[7]=c.w;
    }

    __syncthreads();   // ssinv/smask visible to all

    int pp = 0;                      // parity for the cross-warp partial buffer
    float mcur    = smask[0];
    float sinvcur = ssinv[0];

    for (int t = 0; t < Ss; t++) {
        const int sl = t & (T_TILE - 1);
        const int k  = t >> 2;
        if (sl == 0) {
            asm volatile("cp.async.wait_group 0;\n" ::: "memory");
            __syncthreads();                           // tile k visible; tile k-1 free
            const int nk = k + 1;
            if (nk < NTILES) {
                const float*   srcp = gsrc + (size_t)nk * T_TILE * Hh;
                const uint32_t d = sb_u32 + (uint32_t)((nk & 1) * T_TILE * Hh * 4);
#pragma unroll
                for (int i = 0; i < 8; i++) {
                    int c = tid + i * THREADS;
                    cpa16(d + c * 16, srcp + c * 4);
                }
                asm volatile("cp.async.commit_group;\n");
            }
        }

        // Look-ahead loads: latency hidden under this step's reductions.
        const float mnext    = smask[t + 1];
        const float sinvnext = ssinv[t + 1];

        if (mcur != 0.0f) {          // mask uniform across the block
            const float* sp = sbuf + (k & 1) * (T_TILE * Hh) + sl * Hh;
            float4 s0 = *(const float4*)(sp + tid * 4);
            float4 s1 = *(const float4*)(sp + 512 + tid * 4);
            float sv[8] = {s0.x, s0.y, s0.z, s0.w, s1.x, s1.y, s1.z, s1.w};

            float d0 = 0.0f, d1 = 0.0f, q0 = 0.0f, q1 = 0.0f;
#pragma unroll
            for (int i = 0; i < 4; i++) {
                d0 = fmaf(h[i],     sv[i],     d0);
                d1 = fmaf(h[i + 4], sv[i + 4], d1);
                q0 = fmaf(h[i],     h[i],      q0);
                q1 = fmaf(h[i + 4], h[i + 4],  q1);
            }
            float dot = d0 + d1, hh = q0 + q1;
            // Two independent butterfly chains, explicitly interleaved so the
            // 26-cycle SHFL latencies overlap.
#pragma unroll
            for (int o = 16; o; o >>= 1) {
                float td = __shfl_xor_sync(0xffffffffu, dot, o);
                float th = __shfl_xor_sync(0xffffffffu, hh,  o);
                dot += td;
                hh  += th;
            }
            if (lane == 0) {
                part[pp * 8 + warp * 2]     = dot;
                part[pp * 8 + warp * 2 + 1] = hh;
            }
            __syncthreads();
            float4 p0 = *(const float4*)(part + pp * 8);
            float4 p1 = *(const float4*)(part + pp * 8 + 4);
            float D  = (p0.x + p0.z) + (p1.x + p1.z);
            float HH = (p0.y + p0.w) + (p1.y + p1.w);

            // cos = D / max(||h||*||s||, eps); eps never binds for this data.
            float rsq = rsqrtf(fmaxf(HH, 1e-30f));
            float a   = 1.0f - (D * sinvcur) * rsq;   // h + (s - h*cos) = h*(1-cos) + s
#pragma unroll
            for (int i = 0; i < 8; i++)
                h[i] = fminf(fmaxf(fmaf(h[i], a, sv[i]), -1.0f), 1.0f);
            pp ^= 1;
        } else {
            // reference clips even when mask == 0
#pragma unroll
            for (int i = 0; i < 8; i++)
                h[i] = fminf(fmaxf(h[i], -1.0f), 1.0f);
        }

        mcur    = mnext;
        sinvcur = sinvnext;
    }

    float* o = out + b * Hh;
    *(float4*)(o + tid * 4)       = make_float4(h[0], h[1], h[2], h[3]);
    *(float4*)(o + 512 + tid * 4) = make_float4(h[4], h[5], h[6], h[7]);
}

// ---------------------------------------------------------------------------
extern "C" void kernel_launch(void* const* d_in, const int* in_sizes, int n_in,
                              void* d_out, int out_size) {
    const float* tree = (const float*)d_in[0];   // (B,H)
    const float* seq  = (const float*)d_in[1];   // (B,H,S)
    const float* mask = (const float*)d_in[2];   // (B,S)
    float* out = (float*)d_out;                  // (B,H)

    transpose_kernel<<<dim3(Ss / 32, Hh / 32, Bb), dim3(32, 8)>>>(seq);
    scan_kernel<<<Bb, THREADS>>>(tree, mask, out);
}

// round 8
// speedup vs baseline: 1.3728x; 1.1064x over previous
#include <cuda_runtime.h>
#include <cstdint>

#define Bb 64
#define Hh 1024
#define Ss 512

#define NCHUNK 16                 // s-chunks of 32 steps
#define TBLK_PER_CHUNK 2048       // 64 b * 32 h-blocks
#define SCAN_CTAS Bb
#define THREADS 128

// Scratch: transposed seq_states [B][S][H], per-(b,s,hblk) norm partials, flags.
__device__ float g_trans[(size_t)Bb * Ss * Hh];   // 128 MB
__device__ float g_ssp[Bb * Ss * 32];             // 4 MB (every slot rewritten per launch)
__device__ int   g_flag[NCHUNK];                  // completed transpose blocks per chunk

// ---------------------------------------------------------------------------
__global__ void zero_flags_kernel() {
    if (threadIdx.x < NCHUNK) g_flag[threadIdx.x] = 0;
}

// ---------------------------------------------------------------------------
#define T_TILE 4
#define NTILES (Ss / T_TILE)                          // 128
#define SB_FLOATS (2 * T_TILE * Hh)                   // 8192 floats (32 KB)
#define SMEM_FLOATS (SB_FLOATS + (Ss + 8) + (Ss + 8) + 16)

__device__ __forceinline__ void cpa16(uint32_t dst, const float* src) {
    asm volatile("cp.async.cg.shared.global [%0], [%1], 16;\n" :: "r"(dst), "l"(src));
}

__device__ __forceinline__ void wait_chunk(int c) {
    // tid 0 acquires the flag; bar.sync propagates block-wide.
    if (threadIdx.x == 0) {
        int v;
        asm volatile("ld.acquire.gpu.global.b32 %0, [%1];"
                     : "=r"(v) : "l"(g_flag + c) : "memory");
        while (v < TBLK_PER_CHUNK) {
            __nanosleep(64);
            asm volatile("ld.acquire.gpu.global.b32 %0, [%1];"
                         : "=r"(v) : "l"(g_flag + c) : "memory");
        }
    }
    __syncthreads();
}

// warp 0: compute ssinv for the 32 steps of chunk c (lane -> one s).
__device__ __forceinline__ void compute_ssinv(float* ssinv, int b, int c) {
    int lane = threadIdx.x & 31;
    int s = c * 32 + lane;
    const float4* p = (const float4*)(g_ssp + ((size_t)(b * Ss + s) << 5));
    float acc = 0.0f;
#pragma unroll
    for (int j = 0; j < 8; j++) {
        float4 v = p[j];
        acc += (v.x + v.y) + (v.z + v.w);
    }
    ssinv[s] = rsqrtf(fmaxf(acc, 1e-30f));
}

// ---------------------------------------------------------------------------
// One kernel, two roles:
//   bid 0..63          : scan CTA for batch b = bid (resident from wave 1)
//   bid 64..64+32767   : transpose blocks, s-chunk-major order
// ---------------------------------------------------------------------------
__global__ __launch_bounds__(THREADS, 1)
void fused_kernel(const float* __restrict__ tree,
                  const float* __restrict__ seq,
                  const float* __restrict__ mask_in,
                  float* __restrict__ out) {
    __shared__ float sm[SMEM_FLOATS];
    const int tid = threadIdx.x;

    if (blockIdx.x >= SCAN_CTAS) {
        // ================= transpose role =================
        // 32x32 (s,h) tile with 128 threads (32x4), 8 row-groups each pass.
        float (*tile)[33] = (float(*)[33])sm;
        const int idx = blockIdx.x - SCAN_CTAS;
        const int sb  = idx >> 11;            // chunk  (0..15)
        const int rem = idx & 2047;
        const int b   = rem >> 5;
        const int hb  = rem & 31;
        const int s0  = sb * 32, h0 = hb * 32;
        const int tx  = tid & 31, ty = tid >> 5;     // 32 x 4

        const float* src = seq + (size_t)b * Hh * Ss;
#pragma unroll
        for (int j = 0; j < 8; j++) {
            int hr = ty + j * 4;
            tile[hr][tx] = src[(size_t)(h0 + hr) * Ss + (s0 + tx)];   // coalesced in s
        }
        __syncthreads();

        float* dst = g_trans + (size_t)b * Ss * Hh;
#pragma unroll
        for (int j = 0; j < 8; j++) {
            int sl = ty + j * 4;
            float v = tile[tx][sl];                                   // pad-33: conflict-free
            dst[(size_t)(s0 + sl) * Hh + (h0 + tx)] = v;              // coalesced in h
            float p = v * v;
#pragma unroll
            for (int o = 16; o; o >>= 1) p += __shfl_xor_sync(0xffffffffu, p, o);
            if (tx == 0)
                g_ssp[(size_t)(b * Ss + s0 + sl) * 32 + hb] = p;
        }
        __syncthreads();                 // all stores issued
        if (tid == 0) {
            __threadfence();             // make them visible gpu-wide
            atomicAdd(&g_flag[sb], 1);   // release the chunk
        }
        return;
    }

    // ================= scan role =================
    float* sbuf  = sm;                    // [2][T_TILE*Hh]
    float* ssinv = sm + SB_FLOATS;        // [Ss+8]
    float* smask = ssinv + (Ss + 8);      // [Ss+8]
    float* part  = smask + (Ss + 8);      // [2][8]

    const int b    = blockIdx.x;
    const int lane = tid & 31;
    const int warp = tid >> 5;
    const uint32_t sb_u32 = (uint32_t)__cvta_generic_to_shared(sbuf);
    const float* gsrc = g_trans + (size_t)b * Ss * Hh;

    // Mask preload (input only, no dependency on transpose).
    for (int i = tid; i < Ss; i += THREADS) smask[i] = mask_in[b * Ss + i];
    if (tid < 8) { ssinv[Ss + tid] = 1.0f; smask[Ss + tid] = 0.0f; }   // lookahead pad

    // h state in registers: thread owns h = {tid*4+k, 512+tid*4+k}
    float h[8];
    {
        float4 a = *(const float4*)(tree + b * Hh + tid * 4);
        float4 c = *(const float4*)(tree + b * Hh + 512 + tid * 4);
        h[0]=a.x; h[1]=a.y; h[2]=a.z; h[3]=a.w;
        h[4]=c.x; h[5]=c.y; h[6]=c.z; h[7]=c.w;
    }

    // Wait for chunk 0, then prefetch tile 0 + compute its ssinv.
    wait_chunk(0);
    {
#pragma unroll
        for (int i = 0; i < 8; i++) {
            int c = tid + i * THREADS;
            cpa16(sb_u32 + c * 16, gsrc + c * 4);
        }
        asm volatile("cp.async.commit_group;\n");
    }
    if (warp == 0) compute_ssinv(ssinv, b, 0);
    __syncthreads();    // ssinv chunk0 + smask visible

    int pp = 0;
    float mcur    = smask[0];
    float sinvcur = ssinv[0];
    float4 s0, s1;

    for (int t = 0; t < Ss; t++) {
        const int sl = t & (T_TILE - 1);
        const int k  = t >> 2;
        if (sl == 0) {
            asm volatile("cp.async.wait_group 0;\n" ::: "memory");
            __syncthreads();                           // tile k visible; tile k-1 free
            const int nk = k + 1;
            if (nk < NTILES) {
                if ((nk & 7) == 0) {
                    const int cn = nk >> 3;            // entering chunk cn (1..15)
                    wait_chunk(cn);
                    if (warp == 0) compute_ssinv(ssinv, b, cn);
                    // (consumed from t = 4*nk onward; ordered by next sl==0 barrier)
                }
                const float*   srcp = gsrc + (size_t)nk * T_TILE * Hh;
                const uint32_t d = sb_u32 + (uint32_t)((nk & 1) * T_TILE * Hh * 4);
#pragma unroll
                for (int i = 0; i < 8; i++) {
                    int c = tid + i * THREADS;
                    cpa16(d + c * 16, srcp + c * 4);
                }
                asm volatile("cp.async.commit_group;\n");
            }
            const float* sp = sbuf + (k & 1) * (T_TILE * Hh);
            s0 = *(const float4*)(sp + tid * 4);
            s1 = *(const float4*)(sp + 512 + tid * 4);
        }

        const float mnext    = smask[t + 1];
        const float sinvnext = ssinv[t + 1];
        const float* spn = sbuf + (k & 1) * (T_TILE * Hh) + (sl + 1) * Hh;

        if (mcur != 0.0f) {          // mask uniform across the block
            float sv[8] = {s0.x, s0.y, s0.z, s0.w, s1.x, s1.y, s1.z, s1.w};

            float d0 = 0.0f, d1 = 0.0f, q0 = 0.0f, q1 = 0.0f;
#pragma unroll
            for (int i = 0; i < 4; i++) {
                d0 = fmaf(h[i],     sv[i],     d0);
                d1 = fmaf(h[i + 4], sv[i + 4], d1);
                q0 = fmaf(h[i],     h[i],      q0);
                q1 = fmaf(h[i + 4], h[i + 4],  q1);
            }
            float dot = d0 + d1, hh = q0 + q1;
            // Two independent butterfly chains, explicitly interleaved
            // (redux.sync.add.f32 is NOT supported on sm_103).
#pragma unroll
            for (int o = 16; o; o >>= 1) {
                float td = __shfl_xor_sync(0xffffffffu, dot, o);
                float th = __shfl_xor_sync(0xffffffffu, hh,  o);
                dot += td;
                hh  += th;
            }

            // Prefetch next step's s BEFORE the barrier (ptxas won't hoist
            // LDS across bar.sync) — hides the 29-cyc LDS under the combine.
            if (sl != T_TILE - 1) {
                s0 = *(const float4*)(spn + tid * 4);
                s1 = *(const float4*)(spn + 512 + tid * 4);
            }

            if (lane == 0)
                *(float2*)(part + pp * 8 + warp * 2) = make_float2(dot, hh);
            __syncthreads();
            float4 p0 = *(const float4*)(part + pp * 8);
            float4 p1 = *(const float4*)(part + pp * 8 + 4);
            float D  = (p0.x + p0.z) + (p1.x + p1.z);
            float HH = (p0.y + p0.w) + (p1.y + p1.w);

            // cos = D / max(||h||*||s||, eps); eps never binds for this data.
            float rsq = rsqrtf(fmaxf(HH, 1e-30f));
            float a   = 1.0f - (D * sinvcur) * rsq;   // h*(1-cos) + s
#pragma unroll
            for (int i = 0; i < 8; i++)
                h[i] = fminf(fmaxf(fmaf(h[i], a, sv[i]), -1.0f), 1.0f);
            pp ^= 1;
        } else {
            // reference clips even when mask == 0
#pragma unroll
            for (int i = 0; i < 8; i++)
                h[i] = fminf(fmaxf(h[i], -1.0f), 1.0f);
            if (sl != T_TILE - 1) {
                s0 = *(const float4*)(spn + tid * 4);
                s1 = *(const float4*)(spn + 512 + tid * 4);
            }
        }

        mcur    = mnext;
        sinvcur = sinvnext;
    }

    float* o = out + b * Hh;
    *(float4*)(o + tid * 4)       = make_float4(h[0], h[1], h[2], h[3]);
    *(float4*)(o + 512 + tid * 4) = make_float4(h[4], h[5], h[6], h[7]);
}

// ---------------------------------------------------------------------------
extern "C" void kernel_launch(void* const* d_in, const int* in_sizes, int n_in,
                              void* d_out, int out_size) {
    const float* tree = (const float*)d_in[0];   // (B,H)
    const float* seq  = (const float*)d_in[1];   // (B,H,S)
    const float* mask = (const float*)d_in[2];   // (B,S)
    float* out = (float*)d_out;                  // (B,H)

    zero_flags_kernel<<<1, 32>>>();
    fused_kernel<<<SCAN_CTAS + NCHUNK * TBLK_PER_CHUNK, THREADS>>>(tree, seq, mask, out);
}